// round 4
// baseline (speedup 1.0000x reference)
#include <cuda_runtime.h>
#include <cuda_bf16.h>

// Problem constants (fixed by the reference)
#define BATCH 524288
#define NFEAT 8
#define TPB 256
#define EPT 2

// Fused kernel: each block (redundantly) computes the 27-coeff contraction
// tensor T from the weights while its batch loads are in flight, then applies
// out = sum_{a,b,c} T[a,b,c] * v0_a * v1_b * v2_c, v_i = (1, cos x_i, sin x_i).
__global__ void __launch_bounds__(TPB, 6) vqc_fused_kernel(
    const float4* __restrict__ x4, float* __restrict__ out,
    const float* __restrict__ w) {

    __shared__ float2 sc[18];   // (cos, sin) of 0.5*w[i]
    __shared__ float Vr[8][8];  // Re V[row][col]
    __shared__ float Vi[8][8];  // Im V[row][col]
    __shared__ float sT[27];

    const int tid = threadIdx.x;
    const int base = blockIdx.x * (TPB * EPT) + tid;

    // ---- Issue all batch loads FIRST (independent LDG.128, fly during setup) ----
    float4 xv[EPT];
#pragma unroll
    for (int e = 0; e < EPT; e++) {
        xv[e] = x4[2 * (base + e * TPB)];  // first 16B of each 32B row
    }

    // ---- Stage A (warp 0, lanes 0..17): all 18 half-angle sincos in parallel ----
    if (tid < 18) {
        float c, s;
        __sincosf(0.5f * __ldg(&w[tid]), &s, &c);
        sc[tid] = make_float2(c, s);
    }
    // Zero the scatter target from a DIFFERENT warp (no dependency on warp 0).
    if (tid >= 32 && tid < 32 + 27) {
        sT[tid - 32] = 0.0f;
    }
    if (tid < 32) __syncwarp();

    // ---- Stage B (warp 0, lanes 0..7): simulate column `tid` of V ----
    if (tid < 8) {
        float re[8], im[8];
#pragma unroll
        for (int k = 0; k < 8; k++) { re[k] = 0.0f; im[k] = 0.0f; }
        re[tid] = 1.0f;

#pragma unroll
        for (int l = 0; l < 3; l++) {
#pragma unroll
            for (int q = 0; q < 3; q++) {
                const float2 y = sc[(l * 3 + q) * 2 + 0];  // (cos th/2, sin th/2)
                const float2 z = sc[(l * 3 + q) * 2 + 1];  // (cos ph/2, sin ph/2)
                const float cy = y.x, sy = y.y, cz = z.x, sz = z.y;
                const int bit = 4 >> q;  // qubit q occupies bit (2-q)
#pragma unroll
                for (int j = 0; j < 8; j++) {
                    if (j & bit) continue;
                    const int j1 = j | bit;
                    const float r0 = re[j],  i0 = im[j];
                    const float r1 = re[j1], i1 = im[j1];
                    // RY(th)
                    const float nr0 = cy * r0 - sy * r1;
                    const float ni0 = cy * i0 - sy * i1;
                    const float nr1 = sy * r0 + cy * r1;
                    const float ni1 = sy * i0 + cy * i1;
                    // RZ(ph): amp(bit=0) *= cz - i sz ; amp(bit=1) *= cz + i sz
                    re[j]  = cz * nr0 + sz * ni0;
                    im[j]  = cz * ni0 - sz * nr0;
                    re[j1] = cz * nr1 - sz * ni1;
                    im[j1] = cz * ni1 + sz * nr1;
                }
            }
            // CNOT(0,1): control bit4, target bit2
#pragma unroll
            for (int j = 0; j < 8; j++) {
                if ((j & 4) && !(j & 2)) {
                    const int j1 = j | 2;
                    float tmp;
                    tmp = re[j]; re[j] = re[j1]; re[j1] = tmp;
                    tmp = im[j]; im[j] = im[j1]; im[j1] = tmp;
                }
            }
            // CNOT(1,2): control bit2, target bit1
#pragma unroll
            for (int j = 0; j < 8; j++) {
                if ((j & 2) && !(j & 1)) {
                    const int j1 = j | 1;
                    float tmp;
                    tmp = re[j]; re[j] = re[j1]; re[j1] = tmp;
                    tmp = im[j]; im[j] = im[j1]; im[j1] = tmp;
                }
            }
        }
#pragma unroll
        for (int r = 0; r < 8; r++) { Vr[r][tid] = re[r]; Vi[r][tid] = im[r]; }
    }
    __syncthreads();

    // ---- Stage C (64 threads): M[j][k] then branch-light scatter into sT ----
    if (tid < 64) {
        const int j = tid >> 3, k = tid & 7;
        float m = 0.0f;
#pragma unroll
        for (int r = 0; r < 8; r++) {
            const float zr = (r < 4) ? 1.0f : -1.0f;
            m += zr * (Vr[r][j] * Vr[r][k] + Vi[r][j] * Vi[r][k]);
        }

        // Per-qubit nonzero basis contributions:
        //  diag (jb==kb): basis {0,1}, values {0.5, jb ? -0.5 : 0.5}
        //  off  (jb!=kb): basis {2},   value  {0.5}
        int   nb[3], bas[3][2];
        float val[3][2];
#pragma unroll
        for (int q = 0; q < 3; q++) {
            const int sh = 2 - q;
            const int jb = (j >> sh) & 1, kb = (k >> sh) & 1;
            if (jb == kb) {
                nb[q] = 2;
                bas[q][0] = 0; val[q][0] = 0.5f;
                bas[q][1] = 1; val[q][1] = jb ? -0.5f : 0.5f;
            } else {
                nb[q] = 1;
                bas[q][0] = 2; val[q][0] = 0.5f;
                bas[q][1] = 2; val[q][1] = 0.0f;
            }
        }
        for (int i0 = 0; i0 < nb[0]; i0++)
            for (int i1 = 0; i1 < nb[1]; i1++)
                for (int i2 = 0; i2 < nb[2]; i2++) {
                    const int idx = bas[0][i0] * 9 + bas[1][i1] * 3 + bas[2][i2];
                    atomicAdd(&sT[idx], val[0][i0] * val[1][i1] * val[2][i2] * m);
                }
    }
    __syncthreads();

    // ---- Main compute: T from smem (broadcast), EPT independent chains ----
    float T[27];
#pragma unroll
    for (int i = 0; i < 27; i++) T[i] = sT[i];

#pragma unroll
    for (int e = 0; e < EPT; e++) {
        float c0, s0, c1, s1, c2, s2;
        __sincosf(xv[e].x, &s0, &c0);
        __sincosf(xv[e].y, &s1, &c1);
        __sincosf(xv[e].z, &s2, &c2);

        float u[3];
#pragma unroll
        for (int a = 0; a < 3; a++) {
            float wb[3];
#pragma unroll
            for (int b = 0; b < 3; b++) {
                const float* Tb = &T[a * 9 + b * 3];
                wb[b] = Tb[0] + Tb[1] * c2 + Tb[2] * s2;
            }
            u[a] = wb[0] + wb[1] * c1 + wb[2] * s1;
        }
        out[base + e * TPB] = u[0] + u[1] * c0 + u[2] * s0;
    }
}

extern "C" void kernel_launch(void* const* d_in, const int* in_sizes, int n_in,
                              void* d_out, int out_size) {
    const float* x = (const float*)d_in[0];        // [BATCH, 8]
    const float* w = (const float*)d_in[1];        // [3, 3, 2]
    float* out = (float*)d_out;                    // [BATCH, 1]

    const int nblocks = BATCH / (TPB * EPT);       // 1024
    vqc_fused_kernel<<<nblocks, TPB>>>((const float4*)x, out, w);
}

// round 5
// speedup vs baseline: 1.4391x; 1.4391x over previous
#include <cuda_runtime.h>
#include <cuda_bf16.h>

// Problem constants (fixed by the reference)
#define BATCH 524288
#define NFEAT 8
#define TPB 256
#define EPT 2

// Fused kernel: each block (redundantly) computes the 27-coeff contraction
// tensor T from the weights while its batch loads are in flight, then applies
// out = sum_{a,b,c} T[a,b,c] * v0_a * v1_b * v2_c, v_i = (1, cos x_i, sin x_i).
//
// T = (G (x) G (x) G) . M  with  M = Re(V^H Z0 V)  and per-qubit map
//   g(0,jb,kb) = 0.5*[jb==kb]
//   g(1,jb,kb) = diag: +0.5 (jb=0), -0.5 (jb=1)
//   g(2,jb,kb) = 0.5*[jb!=kb]
// computed as three shallow separable sweeps (48 -> 36 -> 27 outputs),
// branch-free and atomic-free.
__global__ void __launch_bounds__(TPB, 6) vqc_fused_kernel(
    const float4* __restrict__ x4, float* __restrict__ out,
    const float* __restrict__ w) {

    __shared__ float2 sc[18];     // (cos, sin) of 0.5*w[i]
    __shared__ float Vr[8][8];    // Re V[row][col]
    __shared__ float Vi[8][8];    // Im V[row][col]
    __shared__ float Ms[8][8];    // M[j][k]
    __shared__ float Ps[48];      // P[a][r][s], r=j&3, s=k&3
    __shared__ float Qs[36];      // Q[a][b][j0*2+k0]
    __shared__ float sT[27];

    const int tid = threadIdx.x;
    const int base = blockIdx.x * (TPB * EPT) + tid;

    // ---- Issue all batch loads FIRST (independent LDG.128, fly during setup) ----
    float4 xv[EPT];
#pragma unroll
    for (int e = 0; e < EPT; e++) {
        xv[e] = x4[2 * (base + e * TPB)];  // first 16B of each 32B row
    }

    // ---- Warp 0: 18 parallel half-angle sincos, then 8-column circuit sim ----
    if (tid < 32) {
        if (tid < 18) {
            float c, s;
            __sincosf(0.5f * __ldg(&w[tid]), &s, &c);
            sc[tid] = make_float2(c, s);
        }
        __syncwarp();

        if (tid < 8) {
            float re[8], im[8];
#pragma unroll
            for (int k = 0; k < 8; k++) { re[k] = 0.0f; im[k] = 0.0f; }
            re[tid] = 1.0f;

#pragma unroll
            for (int l = 0; l < 3; l++) {
#pragma unroll
                for (int q = 0; q < 3; q++) {
                    const float2 y = sc[(l * 3 + q) * 2 + 0];  // (cos th/2, sin th/2)
                    const float2 z = sc[(l * 3 + q) * 2 + 1];  // (cos ph/2, sin ph/2)
                    const float cy = y.x, sy = y.y, cz = z.x, sz = z.y;
                    const int bit = 4 >> q;  // qubit q occupies bit (2-q)
#pragma unroll
                    for (int j = 0; j < 8; j++) {
                        if (j & bit) continue;
                        const int j1 = j | bit;
                        const float r0 = re[j],  i0 = im[j];
                        const float r1 = re[j1], i1 = im[j1];
                        // RY(th)
                        const float nr0 = cy * r0 - sy * r1;
                        const float ni0 = cy * i0 - sy * i1;
                        const float nr1 = sy * r0 + cy * r1;
                        const float ni1 = sy * i0 + cy * i1;
                        // RZ(ph): amp(bit=0) *= cz - i sz ; amp(bit=1) *= cz + i sz
                        re[j]  = cz * nr0 + sz * ni0;
                        im[j]  = cz * ni0 - sz * nr0;
                        re[j1] = cz * nr1 - sz * ni1;
                        im[j1] = cz * ni1 + sz * nr1;
                    }
                }
                // CNOT(0,1): control bit4, target bit2
#pragma unroll
                for (int j = 0; j < 8; j++) {
                    if ((j & 4) && !(j & 2)) {
                        const int j1 = j | 2;
                        float tmp;
                        tmp = re[j]; re[j] = re[j1]; re[j1] = tmp;
                        tmp = im[j]; im[j] = im[j1]; im[j1] = tmp;
                    }
                }
                // CNOT(1,2): control bit2, target bit1
#pragma unroll
                for (int j = 0; j < 8; j++) {
                    if ((j & 2) && !(j & 1)) {
                        const int j1 = j | 1;
                        float tmp;
                        tmp = re[j]; re[j] = re[j1]; re[j1] = tmp;
                        tmp = im[j]; im[j] = im[j1]; im[j1] = tmp;
                    }
                }
            }
#pragma unroll
            for (int r = 0; r < 8; r++) { Vr[r][tid] = re[r]; Vi[r][tid] = im[r]; }
        }
    }
    __syncthreads();

    // ---- M[j][k] = sum_r z_r * Re(conj(V[r][j]) V[r][k]) ----
    if (tid < 64) {
        const int j = tid >> 3, k = tid & 7;
        float m = 0.0f;
#pragma unroll
        for (int r = 0; r < 8; r++) {
            const float zr = (r < 4) ? 1.0f : -1.0f;
            m += zr * (Vr[r][j] * Vr[r][k] + Vi[r][j] * Vi[r][k]);
        }
        Ms[j][k] = m;
    }
    __syncthreads();

    // ---- Sweep 1 (qubit 0, bit 2): P[a][r][s], 48 outputs, 2 FMAs each ----
    if (tid < 48) {
        const int a = tid >> 4, rem = tid & 15;
        const int r = rem >> 2, s = rem & 3;
        const float m00 = Ms[r][s],     m11 = Ms[4 + r][4 + s];
        const float m01 = Ms[r][4 + s], m10 = Ms[4 + r][s];
        float v;
        if (a == 0)      v = 0.5f * (m00 + m11);
        else if (a == 1) v = 0.5f * (m00 - m11);
        else             v = 0.5f * (m01 + m10);
        Ps[tid] = v;
    }
    __syncthreads();

    // ---- Sweep 2 (qubit 1, bit 1): Q[a][b][j0*2+k0], 36 outputs ----
    if (tid < 36) {
        const int a = tid / 12, rem = tid % 12;
        const int b = rem >> 2, j0 = (rem >> 1) & 1, k0 = rem & 1;
        const float* Pa = &Ps[a * 16];
        const float p00 = Pa[(0 * 2 + j0) * 4 + (0 * 2 + k0)];
        const float p11 = Pa[(1 * 2 + j0) * 4 + (1 * 2 + k0)];
        const float p01 = Pa[(0 * 2 + j0) * 4 + (1 * 2 + k0)];
        const float p10 = Pa[(1 * 2 + j0) * 4 + (0 * 2 + k0)];
        float v;
        if (b == 0)      v = 0.5f * (p00 + p11);
        else if (b == 1) v = 0.5f * (p00 - p11);
        else             v = 0.5f * (p01 + p10);
        Qs[tid] = v;
    }
    __syncthreads();

    // ---- Sweep 3 (qubit 2, bit 0): T[a][b][c], 27 outputs ----
    if (tid < 27) {
        const int a = tid / 9, b = (tid / 3) % 3, c = tid % 3;
        const float* Qab = &Qs[a * 12 + b * 4];
        const float q00 = Qab[0], q01 = Qab[1], q10 = Qab[2], q11 = Qab[3];
        float v;
        if (c == 0)      v = 0.5f * (q00 + q11);
        else if (c == 1) v = 0.5f * (q00 - q11);
        else             v = 0.5f * (q01 + q10);
        sT[tid] = v;
    }
    __syncthreads();

    // ---- Main compute: T from smem (broadcast), EPT independent chains ----
    float T[27];
#pragma unroll
    for (int i = 0; i < 27; i++) T[i] = sT[i];

#pragma unroll
    for (int e = 0; e < EPT; e++) {
        float c0, s0, c1, s1, c2, s2;
        __sincosf(xv[e].x, &s0, &c0);
        __sincosf(xv[e].y, &s1, &c1);
        __sincosf(xv[e].z, &s2, &c2);

        float u[3];
#pragma unroll
        for (int a = 0; a < 3; a++) {
            float wb[3];
#pragma unroll
            for (int b = 0; b < 3; b++) {
                const float* Tb = &T[a * 9 + b * 3];
                wb[b] = Tb[0] + Tb[1] * c2 + Tb[2] * s2;
            }
            u[a] = wb[0] + wb[1] * c1 + wb[2] * s1;
        }
        out[base + e * TPB] = u[0] + u[1] * c0 + u[2] * s0;
    }
}

extern "C" void kernel_launch(void* const* d_in, const int* in_sizes, int n_in,
                              void* d_out, int out_size) {
    const float* x = (const float*)d_in[0];        // [BATCH, 8]
    const float* w = (const float*)d_in[1];        // [3, 3, 2]
    float* out = (float*)d_out;                    // [BATCH, 1]

    const int nblocks = BATCH / (TPB * EPT);       // 1024
    vqc_fused_kernel<<<nblocks, TPB>>>((const float4*)x, out, w);
}

// round 6
// speedup vs baseline: 1.6036x; 1.1143x over previous
#include <cuda_runtime.h>
#include <cuda_bf16.h>

// Problem constants (fixed by the reference)
#define BATCH 524288
#define NFEAT 8
#define TPB 128
#define EPT 4

// Fused kernel: each block (redundantly) computes the 27-coeff contraction
// tensor T from the weights while its batch loads are in flight, then applies
// out = sum_{a,b,c} T[a,b,c] * v0_a * v1_b * v2_c, v_i = (1, cos x_i, sin x_i).
//
// T = (G (x) G (x) G) . M  with  M = Re(V^H Z0 V); computed via three shallow
// separable sweeps (48 -> 36 -> 27 outputs), branch-free and atomic-free.
__global__ void __launch_bounds__(TPB) vqc_fused_kernel(
    const float4* __restrict__ x4, float* __restrict__ out,
    const float* __restrict__ w) {

    __shared__ float2 sc[18];     // (cos, sin) of 0.5*w[i]
    __shared__ float Vr[8][8];    // Re V[row][col]
    __shared__ float Vi[8][8];    // Im V[row][col]
    __shared__ float Ms[8][8];    // M[j][k]
    __shared__ float Ps[48];      // P[a][r][s], r=j&3, s=k&3
    __shared__ float Qs[36];      // Q[a][b][j0*2+k0]
    __shared__ float sT[27];

    const int tid = threadIdx.x;
    const int base = blockIdx.x * (TPB * EPT) + tid;

    // ---- Issue all 4 batch loads FIRST (independent LDG.128, fly during setup) ----
    float4 xv[EPT];
#pragma unroll
    for (int e = 0; e < EPT; e++) {
        xv[e] = x4[2 * (base + e * TPB)];  // first 16B of each 32B row
    }

    // ---- Warp 0: 18 parallel half-angle sincos, then 8-column circuit sim ----
    if (tid < 32) {
        if (tid < 18) {
            float c, s;
            __sincosf(0.5f * __ldg(&w[tid]), &s, &c);
            sc[tid] = make_float2(c, s);
        }
        __syncwarp();

        if (tid < 8) {
            float re[8], im[8];
#pragma unroll
            for (int k = 0; k < 8; k++) { re[k] = 0.0f; im[k] = 0.0f; }
            re[tid] = 1.0f;

#pragma unroll
            for (int l = 0; l < 3; l++) {
#pragma unroll
                for (int q = 0; q < 3; q++) {
                    const float2 y = sc[(l * 3 + q) * 2 + 0];  // (cos th/2, sin th/2)
                    const float2 z = sc[(l * 3 + q) * 2 + 1];  // (cos ph/2, sin ph/2)
                    const float cy = y.x, sy = y.y, cz = z.x, sz = z.y;
                    const int bit = 4 >> q;  // qubit q occupies bit (2-q)
#pragma unroll
                    for (int j = 0; j < 8; j++) {
                        if (j & bit) continue;
                        const int j1 = j | bit;
                        const float r0 = re[j],  i0 = im[j];
                        const float r1 = re[j1], i1 = im[j1];
                        // RY(th)
                        const float nr0 = cy * r0 - sy * r1;
                        const float ni0 = cy * i0 - sy * i1;
                        const float nr1 = sy * r0 + cy * r1;
                        const float ni1 = sy * i0 + cy * i1;
                        // RZ(ph): amp(bit=0) *= cz - i sz ; amp(bit=1) *= cz + i sz
                        re[j]  = cz * nr0 + sz * ni0;
                        im[j]  = cz * ni0 - sz * nr0;
                        re[j1] = cz * nr1 - sz * ni1;
                        im[j1] = cz * ni1 + sz * nr1;
                    }
                }
                // CNOT(0,1): control bit4, target bit2
#pragma unroll
                for (int j = 0; j < 8; j++) {
                    if ((j & 4) && !(j & 2)) {
                        const int j1 = j | 2;
                        float tmp;
                        tmp = re[j]; re[j] = re[j1]; re[j1] = tmp;
                        tmp = im[j]; im[j] = im[j1]; im[j1] = tmp;
                    }
                }
                // CNOT(1,2): control bit2, target bit1
#pragma unroll
                for (int j = 0; j < 8; j++) {
                    if ((j & 2) && !(j & 1)) {
                        const int j1 = j | 1;
                        float tmp;
                        tmp = re[j]; re[j] = re[j1]; re[j1] = tmp;
                        tmp = im[j]; im[j] = im[j1]; im[j1] = tmp;
                    }
                }
            }
#pragma unroll
            for (int r = 0; r < 8; r++) { Vr[r][tid] = re[r]; Vi[r][tid] = im[r]; }
        }
    }
    __syncthreads();

    // ---- M[j][k] = sum_r z_r * Re(conj(V[r][j]) V[r][k]) ----
    if (tid < 64) {
        const int j = tid >> 3, k = tid & 7;
        float m = 0.0f;
#pragma unroll
        for (int r = 0; r < 8; r++) {
            const float zr = (r < 4) ? 1.0f : -1.0f;
            m += zr * (Vr[r][j] * Vr[r][k] + Vi[r][j] * Vi[r][k]);
        }
        Ms[j][k] = m;
    }
    __syncthreads();

    // ---- Sweep 1 (qubit 0, bit 2): P[a][r][s], 48 outputs ----
    if (tid < 48) {
        const int a = tid >> 4, rem = tid & 15;
        const int r = rem >> 2, s = rem & 3;
        const float m00 = Ms[r][s],     m11 = Ms[4 + r][4 + s];
        const float m01 = Ms[r][4 + s], m10 = Ms[4 + r][s];
        float v;
        if (a == 0)      v = 0.5f * (m00 + m11);
        else if (a == 1) v = 0.5f * (m00 - m11);
        else             v = 0.5f * (m01 + m10);
        Ps[tid] = v;
    }
    __syncthreads();

    // ---- Sweep 2 (qubit 1, bit 1): Q[a][b][j0*2+k0], 36 outputs ----
    if (tid < 36) {
        const int a = tid / 12, rem = tid % 12;
        const int b = rem >> 2, j0 = (rem >> 1) & 1, k0 = rem & 1;
        const float* Pa = &Ps[a * 16];
        const float p00 = Pa[(0 * 2 + j0) * 4 + (0 * 2 + k0)];
        const float p11 = Pa[(1 * 2 + j0) * 4 + (1 * 2 + k0)];
        const float p01 = Pa[(0 * 2 + j0) * 4 + (1 * 2 + k0)];
        const float p10 = Pa[(1 * 2 + j0) * 4 + (0 * 2 + k0)];
        float v;
        if (b == 0)      v = 0.5f * (p00 + p11);
        else if (b == 1) v = 0.5f * (p00 - p11);
        else             v = 0.5f * (p01 + p10);
        Qs[tid] = v;
    }
    __syncthreads();

    // ---- Sweep 3 (qubit 2, bit 0): T[a][b][c], 27 outputs ----
    if (tid < 27) {
        const int a = tid / 9, b = (tid / 3) % 3, c = tid % 3;
        const float* Qab = &Qs[a * 12 + b * 4];
        const float q00 = Qab[0], q01 = Qab[1], q10 = Qab[2], q11 = Qab[3];
        float v;
        if (c == 0)      v = 0.5f * (q00 + q11);
        else if (c == 1) v = 0.5f * (q00 - q11);
        else             v = 0.5f * (q01 + q10);
        sT[tid] = v;
    }
    __syncthreads();

    // ---- Main compute: T from smem (broadcast), 4 independent chains ----
    float T[27];
#pragma unroll
    for (int i = 0; i < 27; i++) T[i] = sT[i];

#pragma unroll
    for (int e = 0; e < EPT; e++) {
        float c0, s0, c1, s1, c2, s2;
        __sincosf(xv[e].x, &s0, &c0);
        __sincosf(xv[e].y, &s1, &c1);
        __sincosf(xv[e].z, &s2, &c2);

        float u[3];
#pragma unroll
        for (int a = 0; a < 3; a++) {
            float wb[3];
#pragma unroll
            for (int b = 0; b < 3; b++) {
                const float* Tb = &T[a * 9 + b * 3];
                wb[b] = Tb[0] + Tb[1] * c2 + Tb[2] * s2;
            }
            u[a] = wb[0] + wb[1] * c1 + wb[2] * s1;
        }
        out[base + e * TPB] = u[0] + u[1] * c0 + u[2] * s0;
    }
}

extern "C" void kernel_launch(void* const* d_in, const int* in_sizes, int n_in,
                              void* d_out, int out_size) {
    const float* x = (const float*)d_in[0];        // [BATCH, 8]
    const float* w = (const float*)d_in[1];        // [3, 3, 2]
    float* out = (float*)d_out;                    // [BATCH, 1]

    const int nblocks = BATCH / (TPB * EPT);       // 1024
    vqc_fused_kernel<<<nblocks, TPB>>>((const float4*)x, out, w);
}